// round 15
// baseline (speedup 1.0000x reference)
#include <cuda_runtime.h>
#include <cuda_fp16.h>
#include <math.h>

// Problem constants (fixed shapes)
#define NN   50000
#define EE   800000
#define FIN  128
#define HEADS 8
#define HID  32
#define OUTC 4
#define HC1  (HEADS*HID)   // 256
#define HC2  (HEADS*OUTC)  // 32
#define NEG  0.2f

#define SCAN_B 1024
#define NBLK   ((NN + SCAN_B - 1) / SCAN_B)   // 49
#define NH0   25088                           // half-split boundary (196*128)

// ---------------- scratch (__device__ globals; no runtime allocation) -------
__device__ __half g_h1h[NN * HC1];      // fp16 h1
__device__ __half g_o1h[NN * HC1];      // fp16 o1 (agg1 output)
__device__ __half g_h2h[NN * HC2];      // fp16 h2
__device__ float  g_asrc1[NN * HEADS], g_adst1[NN * HEADS];
__device__ float  g_asrc2[NN * HEADS], g_adst2[NN * HEADS];
__device__ int    g_rowptr[NN + 1];
__device__ int    g_counts[NN];         // zero-init; re-zeroed by scan_finalize
__device__ int    g_rank[EE];
__device__ int    g_csrsrc[EE + NN];
__device__ int    g_blocksums[NBLK + 1];

// ---------------- mma helper -------------------------------------------------
__device__ __forceinline__ void mma16h(float* c, const unsigned* a, const unsigned* b) {
    asm volatile(
        "mma.sync.aligned.m16n8k16.row.col.f32.f16.f16.f32 "
        "{%0,%1,%2,%3}, {%4,%5,%6,%7}, {%8,%9}, {%0,%1,%2,%3};\n"
        : "+f"(c[0]), "+f"(c[1]), "+f"(c[2]), "+f"(c[3])
        : "r"(a[0]), "r"(a[1]), "r"(a[2]), "r"(a[3]), "r"(b[0]), "r"(b[1]));
}
__device__ __forceinline__ unsigned h2pack(float a, float b) {
    __half2 h = __floats2half2_rn(a, b);
    return *(unsigned*)&h;
}

// ===== GEMM1 (2-term fp16-split mma) fused with alphas1 + fp16 output =======
__global__ __launch_bounds__(256, 2)
void gemm1_fused_kernel(int M,
                        const float* __restrict__ A,
                        const float* __restrict__ B,
                        const float* __restrict__ a_src,
                        const float* __restrict__ a_dst,
                        __half* __restrict__ Ch,
                        float* __restrict__ asrc,
                        float* __restrict__ adst) {
    constexpr int BK = 32, K = FIN;
    constexpr int NT = 8;
    constexpr int AP = 18;
    constexpr int BP = 132;

    __shared__ unsigned Ah_s[128 * AP];
    __shared__ unsigned Bh_s[16 * BP], Bl_s[16 * BP];

    const int tid = threadIdx.x;
    const int wid = tid >> 5, lane = tid & 31;
    const int gq = lane >> 2, tig = lane & 3;
    const int warp_m = wid & 3, warp_n = wid >> 2;
    const int blockRow = blockIdx.y * 128;
    const int blockCol = blockIdx.x * 128;

    float acc[2][NT][4];
#pragma unroll
    for (int i = 0; i < 2; i++)
#pragma unroll
        for (int j = 0; j < NT; j++)
#pragma unroll
            for (int r = 0; r < 4; r++) acc[i][j][r] = 0.f;

    for (int k0 = 0; k0 < K; k0 += BK) {
        if (k0) __syncthreads();
#pragma unroll
        for (int l = 0; l < 4; l++) {
            int idx = tid + l * 256;
            int m = idx >> 3, kv = idx & 7;
            int gm = blockRow + m;
            float4 v = (gm < M) ? *(const float4*)&A[(size_t)gm * K + k0 + kv * 4]
                                : make_float4(0.f, 0.f, 0.f, 0.f);
            Ah_s[m * AP + kv * 2 + 0] = h2pack(v.x, v.y);
            Ah_s[m * AP + kv * 2 + 1] = h2pack(v.z, v.w);
        }
#pragma unroll
        for (int l = 0; l < 2; l++) {
            int idx = tid + l * 256;
            int k2 = idx >> 5, n4 = idx & 31;
            const float* r0 = &B[(size_t)(k0 + 2 * k2) * HC1 + blockCol + n4 * 4];
            const float* r1 = r0 + HC1;
            float4 v = *(const float4*)r0;
            float4 w = *(const float4*)r1;
            float va[4] = {v.x, v.y, v.z, v.w};
            float wa[4] = {w.x, w.y, w.z, w.w};
#pragma unroll
            for (int c = 0; c < 4; c++) {
                __half h0 = __float2half_rn(va[c]), h1 = __float2half_rn(wa[c]);
                __half2 hp = __halves2half2(h0, h1);
                Bh_s[k2 * BP + n4 * 4 + c] = *(unsigned*)&hp;
                Bl_s[k2 * BP + n4 * 4 + c] =
                    h2pack(va[c] - __half2float(h0), wa[c] - __half2float(h1));
            }
        }
        __syncthreads();

#pragma unroll
        for (int ks = 0; ks < 2; ks++) {
            const int kh2 = ks * 8;
            unsigned ah[2][4];
#pragma unroll
            for (int i = 0; i < 2; i++) {
                int m0 = warp_m * 32 + i * 16 + gq;
                ah[i][0] = Ah_s[(m0)     * AP + kh2 + tig];
                ah[i][1] = Ah_s[(m0 + 8) * AP + kh2 + tig];
                ah[i][2] = Ah_s[(m0)     * AP + kh2 + 4 + tig];
                ah[i][3] = Ah_s[(m0 + 8) * AP + kh2 + 4 + tig];
            }
#pragma unroll
            for (int j = 0; j < NT; j++) {
                int n = warp_n * 64 + j * 8 + gq;
                unsigned bh[2], bl[2];
                bh[0] = Bh_s[(kh2 + tig)     * BP + n];
                bh[1] = Bh_s[(kh2 + 4 + tig) * BP + n];
                bl[0] = Bl_s[(kh2 + tig)     * BP + n];
                bl[1] = Bl_s[(kh2 + 4 + tig) * BP + n];
#pragma unroll
                for (int i = 0; i < 2; i++) {
                    mma16h(acc[i][j], ah[i], bh);
                    mma16h(acc[i][j], ah[i], bl);
                }
            }
        }
    }

    // ---- fused epilogue ----------------------------------------------------
    float s1[2][2][2], s2[2][2][2];
#pragma unroll
    for (int i = 0; i < 2; i++)
#pragma unroll
        for (int rr = 0; rr < 2; rr++)
#pragma unroll
            for (int g = 0; g < 2; g++) { s1[i][rr][g] = 0.f; s2[i][rr][g] = 0.f; }

    const int headBase = (blockCol >> 5) + warp_n * 2;

#pragma unroll
    for (int j = 0; j < NT; j++) {
        int g = j >> 2;
        int head = headBase + g;
        int lc = (j & 3) * 8 + 2 * tig;
        float2 wsrc = *(const float2*)&a_src[head * HID + lc];
        float2 wdst = *(const float2*)&a_dst[head * HID + lc];
#pragma unroll
        for (int i = 0; i < 2; i++) {
            s1[i][0][g] += acc[i][j][0] * wsrc.x + acc[i][j][1] * wsrc.y;
            s1[i][1][g] += acc[i][j][2] * wsrc.x + acc[i][j][3] * wsrc.y;
            s2[i][0][g] += acc[i][j][0] * wdst.x + acc[i][j][1] * wdst.y;
            s2[i][1][g] += acc[i][j][2] * wdst.x + acc[i][j][3] * wdst.y;
        }
        int coloff = blockCol + warp_n * 64 + j * 8 + 2 * tig;
#pragma unroll
        for (int i = 0; i < 2; i++) {
            int row0 = blockRow + warp_m * 32 + i * 16 + gq;
            if (row0 < M)
                *(__half2*)&Ch[(size_t)row0 * HC1 + coloff] =
                    __floats2half2_rn(acc[i][j][0], acc[i][j][1]);
            if (row0 + 8 < M)
                *(__half2*)&Ch[(size_t)(row0 + 8) * HC1 + coloff] =
                    __floats2half2_rn(acc[i][j][2], acc[i][j][3]);
        }
    }

#pragma unroll
    for (int i = 0; i < 2; i++)
#pragma unroll
        for (int rr = 0; rr < 2; rr++)
#pragma unroll
            for (int g = 0; g < 2; g++) {
                float v1 = s1[i][rr][g], v2 = s2[i][rr][g];
                v1 += __shfl_xor_sync(0xffffffffu, v1, 1);
                v1 += __shfl_xor_sync(0xffffffffu, v1, 2);
                v2 += __shfl_xor_sync(0xffffffffu, v2, 1);
                v2 += __shfl_xor_sync(0xffffffffu, v2, 2);
                if (tig == 0) {
                    int row = blockRow + warp_m * 32 + i * 16 + gq + rr * 8;
                    if (row < M) {
                        asrc[row * HEADS + headBase + g] = v1;
                        adst[row * HEADS + headBase + g] = v2;
                    }
                }
            }
}

// ===== GEMM2 (fp16 mma) fused with alphas2 + fp16 output ====================
__global__ __launch_bounds__(256)
void gemm2_fp16_kernel(int rowBase, int M,
                       const __half* __restrict__ Ah,
                       const float* __restrict__ B,
                       const float* __restrict__ a_src,
                       const float* __restrict__ a_dst,
                       __half* __restrict__ Ch,
                       float* __restrict__ asrc,
                       float* __restrict__ adst) {
    constexpr int BK = 32, K = HC1, N = HC2;
    constexpr int NT = 2;
    constexpr int AP = 18;

    __shared__ unsigned As2[128 * AP];
    __shared__ __half  Bs[32][40];

    const int tid = threadIdx.x;
    const int wid = tid >> 5, lane = tid & 31;
    const int gq = lane >> 2, tig = lane & 3;
    const int warp_m = wid & 3, warp_n = wid >> 2;
    const int blockRow = rowBase + blockIdx.y * 128;

    float acc[2][NT][4];
#pragma unroll
    for (int i = 0; i < 2; i++)
#pragma unroll
        for (int j = 0; j < NT; j++)
#pragma unroll
            for (int r = 0; r < 4; r++) acc[i][j][r] = 0.f;

    for (int k0 = 0; k0 < K; k0 += BK) {
        if (k0) __syncthreads();
#pragma unroll
        for (int l = 0; l < 2; l++) {
            int idx = tid + l * 256;
            int m = idx >> 2, seg = idx & 3;
            int gm = blockRow + m;
            uint4 u = make_uint4(0u, 0u, 0u, 0u);
            if (gm < M) u = *(const uint4*)&Ah[(size_t)gm * K + k0 + seg * 8];
            As2[m * AP + seg * 4 + 0] = u.x;
            As2[m * AP + seg * 4 + 1] = u.y;
            As2[m * AP + seg * 4 + 2] = u.z;
            As2[m * AP + seg * 4 + 3] = u.w;
        }
        {
            int k = tid >> 3, n4 = tid & 7;
            float4 v = *(const float4*)&B[(size_t)(k0 + k) * N + n4 * 4];
            Bs[k][n4 * 4 + 0] = __float2half_rn(v.x);
            Bs[k][n4 * 4 + 1] = __float2half_rn(v.y);
            Bs[k][n4 * 4 + 2] = __float2half_rn(v.z);
            Bs[k][n4 * 4 + 3] = __float2half_rn(v.w);
        }
        __syncthreads();

#pragma unroll
        for (int ks = 0; ks < 2; ks++) {
            const int kh2 = ks * 8;
            const int kk = ks * 16;
            unsigned a[2][4];
#pragma unroll
            for (int i = 0; i < 2; i++) {
                int m0 = warp_m * 32 + i * 16 + gq;
                a[i][0] = As2[(m0)     * AP + kh2 + tig];
                a[i][1] = As2[(m0 + 8) * AP + kh2 + tig];
                a[i][2] = As2[(m0)     * AP + kh2 + 4 + tig];
                a[i][3] = As2[(m0 + 8) * AP + kh2 + 4 + tig];
            }
#pragma unroll
            for (int j = 0; j < NT; j++) {
                int n = warp_n * 16 + j * 8 + gq;
                __half2 hb0 = __halves2half2(Bs[kk + 2 * tig][n], Bs[kk + 2 * tig + 1][n]);
                __half2 hb1 = __halves2half2(Bs[kk + 2 * tig + 8][n], Bs[kk + 2 * tig + 9][n]);
                unsigned b[2] = {*(unsigned*)&hb0, *(unsigned*)&hb1};
#pragma unroll
                for (int i = 0; i < 2; i++)
                    mma16h(acc[i][j], a[i], b);
            }
        }
    }

#pragma unroll
    for (int j = 0; j < NT; j++) {
        int head = warp_n * 4 + 2 * j + (tig >> 1);
        float2 wsrc = *(const float2*)&a_src[head * OUTC + 2 * (tig & 1)];
        float2 wdst = *(const float2*)&a_dst[head * OUTC + 2 * (tig & 1)];
        int coloff = warp_n * 16 + j * 8 + 2 * tig;
#pragma unroll
        for (int i = 0; i < 2; i++) {
#pragma unroll
            for (int rr = 0; rr < 2; rr++) {
                float p1 = acc[i][j][2 * rr] * wsrc.x + acc[i][j][2 * rr + 1] * wsrc.y;
                float p2 = acc[i][j][2 * rr] * wdst.x + acc[i][j][2 * rr + 1] * wdst.y;
                p1 += __shfl_xor_sync(0xffffffffu, p1, 1);
                p2 += __shfl_xor_sync(0xffffffffu, p2, 1);
                int row = blockRow + warp_m * 32 + i * 16 + gq + rr * 8;
                if ((tig & 1) == 0 && row < M) {
                    asrc[row * HEADS + head] = p1;
                    adst[row * HEADS + head] = p2;
                }
            }
            int row0 = blockRow + warp_m * 32 + i * 16 + gq;
            if (row0 < M)
                *(__half2*)&Ch[(size_t)row0 * N + coloff] =
                    __floats2half2_rn(acc[i][j][0], acc[i][j][1]);
            if (row0 + 8 < M)
                *(__half2*)&Ch[(size_t)(row0 + 8) * N + coloff] =
                    __floats2half2_rn(acc[i][j][2], acc[i][j][3]);
        }
    }
}

// ---------------- CSR construction (4 edges/thread for MLP) -----------------
// EE = 800000 divisible by 4.
__global__ void count_kernel(const int* __restrict__ dst) {
    int e4 = blockIdx.x * blockDim.x + threadIdx.x;
    if (e4 * 4 >= EE) return;
    int4 d = ((const int4*)dst)[e4];
    int r0 = atomicAdd(&g_counts[d.x], 1);
    int r1 = atomicAdd(&g_counts[d.y], 1);
    int r2 = atomicAdd(&g_counts[d.z], 1);
    int r3 = atomicAdd(&g_counts[d.w], 1);
    ((int4*)g_rank)[e4] = make_int4(r0, r1, r2, r3);
}

__global__ void scan_blocks_kernel() {
    __shared__ int sh[SCAN_B];
    int t = threadIdx.x;
    int i = blockIdx.x * SCAN_B + t;
    int v = (i < NN) ? (g_counts[i] + 1) : 0;   // +1 self loop
    sh[t] = v;
    __syncthreads();
    for (int off = 1; off < SCAN_B; off <<= 1) {
        int x = (t >= off) ? sh[t - off] : 0;
        __syncthreads();
        sh[t] += x;
        __syncthreads();
    }
    if (i < NN) g_rowptr[i + 1] = sh[t];
    if (t == SCAN_B - 1) g_blocksums[blockIdx.x] = sh[t];
}

__global__ void scan_finalize_kernel() {
    __shared__ int s_off;
    int t = threadIdx.x;
    int sb = (blockIdx.x * 256) / SCAN_B;
    if (t < 32) {
        int v = 0;
        if (t < sb) v += g_blocksums[t];
        if (t + 32 < sb) v += g_blocksums[t + 32];
#pragma unroll
        for (int off = 16; off > 0; off >>= 1)
            v += __shfl_down_sync(0xffffffffu, v, off);
        if (t == 0) s_off = v;
    }
    __syncthreads();
    int i = blockIdx.x * 256 + t;
    if (i == 0) g_rowptr[0] = 0;
    if (i < NN) {
        int e = g_rowptr[i + 1] + s_off;
        g_rowptr[i + 1] = e;
        int begin = e - (g_counts[i] + 1);
        g_csrsrc[begin] = i;        // self loop first
        g_counts[i] = 0;            // re-zero histogram for the next replay
    }
}

__global__ void scatter_kernel(const int* __restrict__ src,
                               const int* __restrict__ dst) {
    int e4 = blockIdx.x * blockDim.x + threadIdx.x;
    if (e4 * 4 >= EE) return;
    int4 d = ((const int4*)dst)[e4];
    int4 s = ((const int4*)src)[e4];
    int4 r = ((const int4*)g_rank)[e4];
    int p0 = g_rowptr[d.x];
    int p1 = g_rowptr[d.y];
    int p2 = g_rowptr[d.z];
    int p3 = g_rowptr[d.w];
    g_csrsrc[p0 + 1 + r.x] = s.x;
    g_csrsrc[p1 + 1 + r.y] = s.y;
    g_csrsrc[p2 + 1 + r.z] = s.z;
    g_csrsrc[p3 + 1 + r.w] = s.w;
}

// ---------------- aggregation: layer 1, warp per node, unroll 2 -------------
__global__ void agg1_kernel(const __half* __restrict__ hh,
                            const float* __restrict__ asrc,
                            const float* __restrict__ adst,
                            const float* __restrict__ bias,
                            __half* __restrict__ outh,
                            int nodeBase, int nodeEnd) {
    int node = nodeBase + ((blockIdx.x * blockDim.x + threadIdx.x) >> 5);
    int lane = threadIdx.x & 31;
    if (node >= nodeEnd) return;

    int beg = g_rowptr[node];
    int end = g_rowptr[node + 1];
    int hsel = lane >> 2;

    float adst_l = adst[node * HEADS + hsel];
    float tt = asrc[node * HEADS + hsel] + adst_l;
    float aself = (tt > 0.f) ? tt : NEG * tt;   // self-loop logit = stabilizer

    float denom = 0.f;
    float acc[8];
#pragma unroll
    for (int r = 0; r < 8; r++) acc[r] = 0.f;

    int j = beg;
    for (; j + 1 < end; j += 2) {
        int s0 = g_csrsrc[j];
        int s1v = g_csrsrc[j + 1];
        float a0 = asrc[s0 * HEADS + hsel] + adst_l;
        float a1 = asrc[s1v * HEADS + hsel] + adst_l;
        uint4 u0 = *((const uint4*)(hh + (size_t)s0 * HC1) + lane);
        uint4 u1 = *((const uint4*)(hh + (size_t)s1v * HC1) + lane);
        a0 = (a0 > 0.f) ? a0 : NEG * a0;
        a1 = (a1 > 0.f) ? a1 : NEG * a1;
        float ex0 = __expf(fminf(a0 - aself, 60.f));
        float ex1 = __expf(fminf(a1 - aself, 60.f));
        denom += ex0 + ex1;
        float2 f;
        f = __half22float2(*(__half2*)&u0.x); acc[0] = fmaf(f.x, ex0, acc[0]); acc[1] = fmaf(f.y, ex0, acc[1]);
        f = __half22float2(*(__half2*)&u0.y); acc[2] = fmaf(f.x, ex0, acc[2]); acc[3] = fmaf(f.y, ex0, acc[3]);
        f = __half22float2(*(__half2*)&u0.z); acc[4] = fmaf(f.x, ex0, acc[4]); acc[5] = fmaf(f.y, ex0, acc[5]);
        f = __half22float2(*(__half2*)&u0.w); acc[6] = fmaf(f.x, ex0, acc[6]); acc[7] = fmaf(f.y, ex0, acc[7]);
        f = __half22float2(*(__half2*)&u1.x); acc[0] = fmaf(f.x, ex1, acc[0]); acc[1] = fmaf(f.y, ex1, acc[1]);
        f = __half22float2(*(__half2*)&u1.y); acc[2] = fmaf(f.x, ex1, acc[2]); acc[3] = fmaf(f.y, ex1, acc[3]);
        f = __half22float2(*(__half2*)&u1.z); acc[4] = fmaf(f.x, ex1, acc[4]); acc[5] = fmaf(f.y, ex1, acc[5]);
        f = __half22float2(*(__half2*)&u1.w); acc[6] = fmaf(f.x, ex1, acc[6]); acc[7] = fmaf(f.y, ex1, acc[7]);
    }
    if (j < end) {
        int s = g_csrsrc[j];
        float a = asrc[s * HEADS + hsel] + adst_l;
        a = (a > 0.f) ? a : NEG * a;
        float ex = __expf(fminf(a - aself, 60.f));
        denom += ex;
        uint4 u = *((const uint4*)(hh + (size_t)s * HC1) + lane);
        float2 f;
        f = __half22float2(*(__half2*)&u.x); acc[0] = fmaf(f.x, ex, acc[0]); acc[1] = fmaf(f.y, ex, acc[1]);
        f = __half22float2(*(__half2*)&u.y); acc[2] = fmaf(f.x, ex, acc[2]); acc[3] = fmaf(f.y, ex, acc[3]);
        f = __half22float2(*(__half2*)&u.z); acc[4] = fmaf(f.x, ex, acc[4]); acc[5] = fmaf(f.y, ex, acc[5]);
        f = __half22float2(*(__half2*)&u.w); acc[6] = fmaf(f.x, ex, acc[6]); acc[7] = fmaf(f.y, ex, acc[7]);
    }

    float d = denom + 1e-16f;
    const float4* b4 = (const float4*)bias + lane * 2;
    float4 bb0 = b4[0], bb1 = b4[1];
    float o[8];
    o[0] = acc[0] / d + bb0.x; o[1] = acc[1] / d + bb0.y;
    o[2] = acc[2] / d + bb0.z; o[3] = acc[3] / d + bb0.w;
    o[4] = acc[4] / d + bb1.x; o[5] = acc[5] / d + bb1.y;
    o[6] = acc[6] / d + bb1.z; o[7] = acc[7] / d + bb1.w;
#pragma unroll
    for (int r = 0; r < 8; r++) o[r] = (o[r] > 0.f) ? o[r] : NEG * o[r];

    __half2 ho[4];
    ho[0] = __floats2half2_rn(o[0], o[1]);
    ho[1] = __floats2half2_rn(o[2], o[3]);
    ho[2] = __floats2half2_rn(o[4], o[5]);
    ho[3] = __floats2half2_rn(o[6], o[7]);
    *(uint4*)(outh + (size_t)node * HC1 + lane * 8) = *(uint4*)ho;
}

// ---------------- aggregation: layer 2 (C=4), fp16 gather, unroll 4 ---------
__global__ void agg2_kernel(const __half* __restrict__ hh,
                            const float* __restrict__ asrc,
                            const float* __restrict__ adst,
                            const float* __restrict__ bias,
                            float* __restrict__ out) {
    int warp = (blockIdx.x * blockDim.x + threadIdx.x) >> 5;
    int lane = threadIdx.x & 31;
    if (warp >= NN) return;

    int beg = g_rowptr[warp];
    int end = g_rowptr[warp + 1];
    int hd = lane >> 2;

    float adst_l = adst[warp * HEADS + hd];
    float tt = asrc[warp * HEADS + hd] + adst_l;
    float aself = (tt > 0.f) ? tt : NEG * tt;

    float denom = 0.f;
    float acc = 0.f;
    int j = beg;
    for (; j + 3 < end; j += 4) {
        int s0 = g_csrsrc[j], s1 = g_csrsrc[j + 1];
        int s2v = g_csrsrc[j + 2], s3 = g_csrsrc[j + 3];
        float a0 = asrc[s0 * HEADS + hd] + adst_l;
        float a1 = asrc[s1 * HEADS + hd] + adst_l;
        float a2 = asrc[s2v * HEADS + hd] + adst_l;
        float a3 = asrc[s3 * HEADS + hd] + adst_l;
        float v0 = __half2float(hh[(size_t)s0 * HC2 + lane]);
        float v1 = __half2float(hh[(size_t)s1 * HC2 + lane]);
        float v2 = __half2float(hh[(size_t)s2v * HC2 + lane]);
        float v3 = __half2float(hh[(size_t)s3 * HC2 + lane]);
        a0 = (a0 > 0.f) ? a0 : NEG * a0;
        a1 = (a1 > 0.f) ? a1 : NEG * a1;
        a2 = (a2 > 0.f) ? a2 : NEG * a2;
        a3 = (a3 > 0.f) ? a3 : NEG * a3;
        float ex0 = __expf(fminf(a0 - aself, 60.f));
        float ex1 = __expf(fminf(a1 - aself, 60.f));
        float ex2 = __expf(fminf(a2 - aself, 60.f));
        float ex3 = __expf(fminf(a3 - aself, 60.f));
        denom += (ex0 + ex1) + (ex2 + ex3);
        acc = fmaf(v0, ex0, acc);
        acc = fmaf(v1, ex1, acc);
        acc = fmaf(v2, ex2, acc);
        acc = fmaf(v3, ex3, acc);
    }
    for (; j < end; j++) {
        int s = g_csrsrc[j];
        float a = asrc[s * HEADS + hd] + adst_l;
        a = (a > 0.f) ? a : NEG * a;
        float ex = __expf(fminf(a - aself, 60.f));
        denom += ex;
        acc = fmaf(__half2float(hh[(size_t)s * HC2 + lane]), ex, acc);
    }

    out[(size_t)warp * HC2 + lane] = acc / (denom + 1e-16f) + bias[lane];
}

// ---------------- launch ------------------------------------------------------
extern "C" void kernel_launch(void* const* d_in, const int* in_sizes, int n_in,
                              void* d_out, int out_size) {
    const float* x      = (const float*)d_in[0];
    const int*   ei     = (const int*)d_in[1];
    const float* W1     = (const float*)d_in[2];
    const float* a_src1 = (const float*)d_in[3];
    const float* a_dst1 = (const float*)d_in[4];
    const float* b1     = (const float*)d_in[5];
    const float* W2     = (const float*)d_in[6];
    const float* a_src2 = (const float*)d_in[7];
    const float* a_dst2 = (const float*)d_in[8];
    const float* b2     = (const float*)d_in[9];
    float* out = (float*)d_out;

    const int* src = ei;
    const int* dst = ei + EE;

    float *as1, *ad1, *as2, *ad2;
    __half *h1h, *o1h, *h2h;
    cudaGetSymbolAddress((void**)&h1h, g_h1h);
    cudaGetSymbolAddress((void**)&o1h, g_o1h);
    cudaGetSymbolAddress((void**)&h2h, g_h2h);
    cudaGetSymbolAddress((void**)&as1, g_asrc1);
    cudaGetSymbolAddress((void**)&ad1, g_adst1);
    cudaGetSymbolAddress((void**)&as2, g_asrc2);
    cudaGetSymbolAddress((void**)&ad2, g_adst2);

    static cudaStream_t s2 = nullptr;
    static cudaEvent_t evFork = nullptr, evJoin = nullptr, evA = nullptr, evB = nullptr;
    if (s2 == nullptr) {
        cudaStreamCreateWithFlags(&s2, cudaStreamNonBlocking);
        cudaEventCreateWithFlags(&evFork, cudaEventDisableTiming);
        cudaEventCreateWithFlags(&evJoin, cudaEventDisableTiming);
        cudaEventCreateWithFlags(&evA, cudaEventDisableTiming);
        cudaEventCreateWithFlags(&evB, cudaEventDisableTiming);
    }

    // --- fork: CSR build on s2 (counts pre-zeroed by previous finalize),
    //     GEMM1 on main stream --------------------------------------------------
    cudaEventRecord(evFork, 0);
    cudaStreamWaitEvent(s2, evFork, 0);

    count_kernel<<<(EE / 4 + 255) / 256, 256, 0, s2>>>(dst);
    scan_blocks_kernel<<<NBLK, SCAN_B, 0, s2>>>();
    scan_finalize_kernel<<<(NN + 255) / 256, 256, 0, s2>>>();
    scatter_kernel<<<(EE / 4 + 255) / 256, 256, 0, s2>>>(src, dst);
    cudaEventRecord(evJoin, s2);

    // main stream: GEMM1
    {
        dim3 grid(2, (NN + 127) / 128);
        gemm1_fused_kernel<<<grid, 256>>>(NN, x, W1, a_src1, a_dst1,
                                          h1h, as1, ad1);
    }

    // --- join, then half-split agg1 / gemm2 pipeline --------------------------
    cudaStreamWaitEvent(0, evJoin, 0);
    agg1_kernel<<<(NH0 * 32 + 255) / 256, 256>>>(h1h, as1, ad1, b1, o1h, 0, NH0);
    cudaEventRecord(evA, 0);
    agg1_kernel<<<((NN - NH0) * 32 + 255) / 256, 256>>>(h1h, as1, ad1, b1, o1h, NH0, NN);

    // side stream: gemm2 on first half (overlaps agg1 second half)
    cudaStreamWaitEvent(s2, evA, 0);
    {
        dim3 grid(1, NH0 / 128);
        gemm2_fp16_kernel<<<grid, 256, 0, s2>>>(0, NN, o1h, W2, a_src2, a_dst2,
                                                h2h, as2, ad2);
    }
    cudaEventRecord(evB, s2);

    // main stream: gemm2 on second half
    {
        dim3 grid(1, (NN - NH0 + 127) / 128);
        gemm2_fp16_kernel<<<grid, 256>>>(NH0, NN, o1h, W2, a_src2, a_dst2,
                                         h2h, as2, ad2);
    }

    // --- join both gemm2 halves, then agg2 -------------------------------------
    cudaStreamWaitEvent(0, evB, 0);
    agg2_kernel<<<(NN * 32 + 255) / 256, 256>>>(h2h, as2, ad2, b2, out);
}

// round 16
// speedup vs baseline: 1.0126x; 1.0126x over previous
#include <cuda_runtime.h>
#include <cuda_fp16.h>
#include <math.h>

// Problem constants (fixed shapes)
#define NN   50000
#define EE   800000
#define FIN  128
#define HEADS 8
#define HID  32
#define OUTC 4
#define HC1  (HEADS*HID)   // 256
#define HC2  (HEADS*OUTC)  // 32
#define NEG  0.2f

#define SCAN_B 1024
#define NBLK   ((NN + SCAN_B - 1) / SCAN_B)   // 49
#define NH0   25088                           // half-split boundary (196*128)

// ---------------- scratch (__device__ globals; no runtime allocation) -------
__device__ __half g_h1h[NN * HC1];      // fp16 h1
__device__ __half g_o1h[NN * HC1];      // fp16 o1 (agg1 output)
__device__ __half g_h2h[NN * HC2];      // fp16 h2
__device__ float  g_asrc1[NN * HEADS], g_adst1[NN * HEADS];
__device__ float  g_asrc2[NN * HEADS], g_adst2[NN * HEADS];
__device__ int    g_rowptr[NN + 1];
__device__ int    g_counts[NN];         // zero-init; re-zeroed by scan_fused
__device__ int    g_rank[EE];
__device__ int    g_csrsrc[EE + NN];
__device__ int    g_aggflag[2][NBLK];   // lookback flags (value+1), parity slots
__device__ int    g_runpar;             // toggled once per launch by count_kernel

// ---------------- mma helper -------------------------------------------------
__device__ __forceinline__ void mma16h(float* c, const unsigned* a, const unsigned* b) {
    asm volatile(
        "mma.sync.aligned.m16n8k16.row.col.f32.f16.f16.f32 "
        "{%0,%1,%2,%3}, {%4,%5,%6,%7}, {%8,%9}, {%0,%1,%2,%3};\n"
        : "+f"(c[0]), "+f"(c[1]), "+f"(c[2]), "+f"(c[3])
        : "r"(a[0]), "r"(a[1]), "r"(a[2]), "r"(a[3]), "r"(b[0]), "r"(b[1]));
}
__device__ __forceinline__ unsigned h2pack(float a, float b) {
    __half2 h = __floats2half2_rn(a, b);
    return *(unsigned*)&h;
}

// ===== GEMM1 (2-term fp16-split mma) fused with alphas1 + fp16 output =======
__global__ __launch_bounds__(256, 2)
void gemm1_fused_kernel(int M,
                        const float* __restrict__ A,
                        const float* __restrict__ B,
                        const float* __restrict__ a_src,
                        const float* __restrict__ a_dst,
                        __half* __restrict__ Ch,
                        float* __restrict__ asrc,
                        float* __restrict__ adst) {
    constexpr int BK = 32, K = FIN;
    constexpr int NT = 8;
    constexpr int AP = 18;
    constexpr int BP = 132;

    __shared__ unsigned Ah_s[128 * AP];
    __shared__ unsigned Bh_s[16 * BP], Bl_s[16 * BP];

    const int tid = threadIdx.x;
    const int wid = tid >> 5, lane = tid & 31;
    const int gq = lane >> 2, tig = lane & 3;
    const int warp_m = wid & 3, warp_n = wid >> 2;
    const int blockRow = blockIdx.y * 128;
    const int blockCol = blockIdx.x * 128;

    float acc[2][NT][4];
#pragma unroll
    for (int i = 0; i < 2; i++)
#pragma unroll
        for (int j = 0; j < NT; j++)
#pragma unroll
            for (int r = 0; r < 4; r++) acc[i][j][r] = 0.f;

    for (int k0 = 0; k0 < K; k0 += BK) {
        if (k0) __syncthreads();
#pragma unroll
        for (int l = 0; l < 4; l++) {
            int idx = tid + l * 256;
            int m = idx >> 3, kv = idx & 7;
            int gm = blockRow + m;
            float4 v = (gm < M) ? *(const float4*)&A[(size_t)gm * K + k0 + kv * 4]
                                : make_float4(0.f, 0.f, 0.f, 0.f);
            Ah_s[m * AP + kv * 2 + 0] = h2pack(v.x, v.y);
            Ah_s[m * AP + kv * 2 + 1] = h2pack(v.z, v.w);
        }
#pragma unroll
        for (int l = 0; l < 2; l++) {
            int idx = tid + l * 256;
            int k2 = idx >> 5, n4 = idx & 31;
            const float* r0 = &B[(size_t)(k0 + 2 * k2) * HC1 + blockCol + n4 * 4];
            const float* r1 = r0 + HC1;
            float4 v = *(const float4*)r0;
            float4 w = *(const float4*)r1;
            float va[4] = {v.x, v.y, v.z, v.w};
            float wa[4] = {w.x, w.y, w.z, w.w};
#pragma unroll
            for (int c = 0; c < 4; c++) {
                __half h0 = __float2half_rn(va[c]), h1 = __float2half_rn(wa[c]);
                __half2 hp = __halves2half2(h0, h1);
                Bh_s[k2 * BP + n4 * 4 + c] = *(unsigned*)&hp;
                Bl_s[k2 * BP + n4 * 4 + c] =
                    h2pack(va[c] - __half2float(h0), wa[c] - __half2float(h1));
            }
        }
        __syncthreads();

#pragma unroll
        for (int ks = 0; ks < 2; ks++) {
            const int kh2 = ks * 8;
            unsigned ah[2][4];
#pragma unroll
            for (int i = 0; i < 2; i++) {
                int m0 = warp_m * 32 + i * 16 + gq;
                ah[i][0] = Ah_s[(m0)     * AP + kh2 + tig];
                ah[i][1] = Ah_s[(m0 + 8) * AP + kh2 + tig];
                ah[i][2] = Ah_s[(m0)     * AP + kh2 + 4 + tig];
                ah[i][3] = Ah_s[(m0 + 8) * AP + kh2 + 4 + tig];
            }
#pragma unroll
            for (int j = 0; j < NT; j++) {
                int n = warp_n * 64 + j * 8 + gq;
                unsigned bh[2], bl[2];
                bh[0] = Bh_s[(kh2 + tig)     * BP + n];
                bh[1] = Bh_s[(kh2 + 4 + tig) * BP + n];
                bl[0] = Bl_s[(kh2 + tig)     * BP + n];
                bl[1] = Bl_s[(kh2 + 4 + tig) * BP + n];
#pragma unroll
                for (int i = 0; i < 2; i++) {
                    mma16h(acc[i][j], ah[i], bh);
                    mma16h(acc[i][j], ah[i], bl);
                }
            }
        }
    }

    // ---- fused epilogue ----------------------------------------------------
    float s1[2][2][2], s2[2][2][2];
#pragma unroll
    for (int i = 0; i < 2; i++)
#pragma unroll
        for (int rr = 0; rr < 2; rr++)
#pragma unroll
            for (int g = 0; g < 2; g++) { s1[i][rr][g] = 0.f; s2[i][rr][g] = 0.f; }

    const int headBase = (blockCol >> 5) + warp_n * 2;

#pragma unroll
    for (int j = 0; j < NT; j++) {
        int g = j >> 2;
        int head = headBase + g;
        int lc = (j & 3) * 8 + 2 * tig;
        float2 wsrc = *(const float2*)&a_src[head * HID + lc];
        float2 wdst = *(const float2*)&a_dst[head * HID + lc];
#pragma unroll
        for (int i = 0; i < 2; i++) {
            s1[i][0][g] += acc[i][j][0] * wsrc.x + acc[i][j][1] * wsrc.y;
            s1[i][1][g] += acc[i][j][2] * wsrc.x + acc[i][j][3] * wsrc.y;
            s2[i][0][g] += acc[i][j][0] * wdst.x + acc[i][j][1] * wdst.y;
            s2[i][1][g] += acc[i][j][2] * wdst.x + acc[i][j][3] * wdst.y;
        }
        int coloff = blockCol + warp_n * 64 + j * 8 + 2 * tig;
#pragma unroll
        for (int i = 0; i < 2; i++) {
            int row0 = blockRow + warp_m * 32 + i * 16 + gq;
            if (row0 < M)
                *(__half2*)&Ch[(size_t)row0 * HC1 + coloff] =
                    __floats2half2_rn(acc[i][j][0], acc[i][j][1]);
            if (row0 + 8 < M)
                *(__half2*)&Ch[(size_t)(row0 + 8) * HC1 + coloff] =
                    __floats2half2_rn(acc[i][j][2], acc[i][j][3]);
        }
    }

#pragma unroll
    for (int i = 0; i < 2; i++)
#pragma unroll
        for (int rr = 0; rr < 2; rr++)
#pragma unroll
            for (int g = 0; g < 2; g++) {
                float v1 = s1[i][rr][g], v2 = s2[i][rr][g];
                v1 += __shfl_xor_sync(0xffffffffu, v1, 1);
                v1 += __shfl_xor_sync(0xffffffffu, v1, 2);
                v2 += __shfl_xor_sync(0xffffffffu, v2, 1);
                v2 += __shfl_xor_sync(0xffffffffu, v2, 2);
                if (tig == 0) {
                    int row = blockRow + warp_m * 32 + i * 16 + gq + rr * 8;
                    if (row < M) {
                        asrc[row * HEADS + headBase + g] = v1;
                        adst[row * HEADS + headBase + g] = v2;
                    }
                }
            }
}

// ===== GEMM2 (fp16 mma) fused with alphas2 + fp16 output ====================
__global__ __launch_bounds__(256)
void gemm2_fp16_kernel(int rowBase, int M,
                       const __half* __restrict__ Ah,
                       const float* __restrict__ B,
                       const float* __restrict__ a_src,
                       const float* __restrict__ a_dst,
                       __half* __restrict__ Ch,
                       float* __restrict__ asrc,
                       float* __restrict__ adst) {
    constexpr int BK = 32, K = HC1, N = HC2;
    constexpr int NT = 2;
    constexpr int AP = 18;

    __shared__ unsigned As2[128 * AP];
    __shared__ __half  Bs[32][40];

    const int tid = threadIdx.x;
    const int wid = tid >> 5, lane = tid & 31;
    const int gq = lane >> 2, tig = lane & 3;
    const int warp_m = wid & 3, warp_n = wid >> 2;
    const int blockRow = rowBase + blockIdx.y * 128;

    float acc[2][NT][4];
#pragma unroll
    for (int i = 0; i < 2; i++)
#pragma unroll
        for (int j = 0; j < NT; j++)
#pragma unroll
            for (int r = 0; r < 4; r++) acc[i][j][r] = 0.f;

    for (int k0 = 0; k0 < K; k0 += BK) {
        if (k0) __syncthreads();
#pragma unroll
        for (int l = 0; l < 2; l++) {
            int idx = tid + l * 256;
            int m = idx >> 2, seg = idx & 3;
            int gm = blockRow + m;
            uint4 u = make_uint4(0u, 0u, 0u, 0u);
            if (gm < M) u = *(const uint4*)&Ah[(size_t)gm * K + k0 + seg * 8];
            As2[m * AP + seg * 4 + 0] = u.x;
            As2[m * AP + seg * 4 + 1] = u.y;
            As2[m * AP + seg * 4 + 2] = u.z;
            As2[m * AP + seg * 4 + 3] = u.w;
        }
        {
            int k = tid >> 3, n4 = tid & 7;
            float4 v = *(const float4*)&B[(size_t)(k0 + k) * N + n4 * 4];
            Bs[k][n4 * 4 + 0] = __float2half_rn(v.x);
            Bs[k][n4 * 4 + 1] = __float2half_rn(v.y);
            Bs[k][n4 * 4 + 2] = __float2half_rn(v.z);
            Bs[k][n4 * 4 + 3] = __float2half_rn(v.w);
        }
        __syncthreads();

#pragma unroll
        for (int ks = 0; ks < 2; ks++) {
            const int kh2 = ks * 8;
            const int kk = ks * 16;
            unsigned a[2][4];
#pragma unroll
            for (int i = 0; i < 2; i++) {
                int m0 = warp_m * 32 + i * 16 + gq;
                a[i][0] = As2[(m0)     * AP + kh2 + tig];
                a[i][1] = As2[(m0 + 8) * AP + kh2 + tig];
                a[i][2] = As2[(m0)     * AP + kh2 + 4 + tig];
                a[i][3] = As2[(m0 + 8) * AP + kh2 + 4 + tig];
            }
#pragma unroll
            for (int j = 0; j < NT; j++) {
                int n = warp_n * 16 + j * 8 + gq;
                __half2 hb0 = __halves2half2(Bs[kk + 2 * tig][n], Bs[kk + 2 * tig + 1][n]);
                __half2 hb1 = __halves2half2(Bs[kk + 2 * tig + 8][n], Bs[kk + 2 * tig + 9][n]);
                unsigned b[2] = {*(unsigned*)&hb0, *(unsigned*)&hb1};
#pragma unroll
                for (int i = 0; i < 2; i++)
                    mma16h(acc[i][j], a[i], b);
            }
        }
    }

#pragma unroll
    for (int j = 0; j < NT; j++) {
        int head = warp_n * 4 + 2 * j + (tig >> 1);
        float2 wsrc = *(const float2*)&a_src[head * OUTC + 2 * (tig & 1)];
        float2 wdst = *(const float2*)&a_dst[head * OUTC + 2 * (tig & 1)];
        int coloff = warp_n * 16 + j * 8 + 2 * tig;
#pragma unroll
        for (int i = 0; i < 2; i++) {
#pragma unroll
            for (int rr = 0; rr < 2; rr++) {
                float p1 = acc[i][j][2 * rr] * wsrc.x + acc[i][j][2 * rr + 1] * wsrc.y;
                float p2 = acc[i][j][2 * rr] * wdst.x + acc[i][j][2 * rr + 1] * wdst.y;
                p1 += __shfl_xor_sync(0xffffffffu, p1, 1);
                p2 += __shfl_xor_sync(0xffffffffu, p2, 1);
                int row = blockRow + warp_m * 32 + i * 16 + gq + rr * 8;
                if ((tig & 1) == 0 && row < M) {
                    asrc[row * HEADS + head] = p1;
                    adst[row * HEADS + head] = p2;
                }
            }
            int row0 = blockRow + warp_m * 32 + i * 16 + gq;
            if (row0 < M)
                *(__half2*)&Ch[(size_t)row0 * N + coloff] =
                    __floats2half2_rn(acc[i][j][0], acc[i][j][1]);
            if (row0 + 8 < M)
                *(__half2*)&Ch[(size_t)(row0 + 8) * N + coloff] =
                    __floats2half2_rn(acc[i][j][2], acc[i][j][3]);
        }
    }
}

// ---------------- CSR construction ------------------------------------------
// count: 1 edge/thread (round-14 proven) + per-launch parity toggle.
__global__ void count_kernel(const int* __restrict__ dst) {
    int e = blockIdx.x * blockDim.x + threadIdx.x;
    if (e == 0) g_runpar ^= 1;   // once per launch; consumed by scan_fused later
    if (e < EE) g_rank[e] = atomicAdd(&g_counts[dst[e]], 1);
}

// Fused block-scan + aggregate-lookback + finalize. grid = NBLK, block = 1024.
// Each block publishes its local sum to g_aggflag[par][b] (value+1), then
// warp-sums all lower blocks' aggregates (spin until published). Blocks only
// wait on lower bids (launched first) -> no circular wait. Parity slots make
// this graph-replay safe; each run clears the other slot for the next run.
__global__ void scan_fused_kernel() {
    __shared__ int sh[SCAN_B];
    __shared__ int s_off;
    const int t = threadIdx.x;
    const int b = blockIdx.x;
    const int par = g_runpar & 1;
    int i = b * SCAN_B + t;
    int v = (i < NN) ? (g_counts[i] + 1) : 0;   // +1 self loop
    sh[t] = v;
    __syncthreads();
    for (int off = 1; off < SCAN_B; off <<= 1) {
        int x = (t >= off) ? sh[t - off] : 0;
        __syncthreads();
        sh[t] += x;
        __syncthreads();
    }
    // publish this block's aggregate (inclusive total), as value+1
    if (t == 0) {
        int total = sh[SCAN_B - 1];
        __threadfence();
        atomicExch(&g_aggflag[par][b], total + 1);
    }
    // lookback: sum aggregates of blocks [0, b)
    if (t < 32) {
        int sum = 0;
        for (int q = t; q < b; q += 32) {
            int f;
            do { f = atomicAdd(&g_aggflag[par][q], 0); } while (f == 0);
            sum += f - 1;
        }
#pragma unroll
        for (int o = 16; o > 0; o >>= 1)
            sum += __shfl_down_sync(0xffffffffu, sum, o);
        if (t == 0) s_off = sum;
    }
    __syncthreads();
    int off = s_off;
    if (i == 0) g_rowptr[0] = 0;
    if (i < NN) {
        int e = sh[t] + off;
        g_rowptr[i + 1] = e;
        int begin = e - v;
        g_csrsrc[begin] = i;        // self loop first
        g_counts[i] = 0;            // re-zero histogram for the next replay
    }
    if (t == 0) g_aggflag[par ^ 1][b] = 0;   // clear other slot for next run
}

// scatter: 1 edge/thread (round-14 proven).
__global__ void scatter_kernel(const int* __restrict__ src,
                               const int* __restrict__ dst) {
    int e = blockIdx.x * blockDim.x + threadIdx.x;
    if (e < EE) {
        int d = dst[e];
        g_csrsrc[g_rowptr[d] + 1 + g_rank[e]] = src[e];
    }
}

// ---------------- aggregation: layer 1, warp per node, unroll 2 -------------
__global__ void agg1_kernel(const __half* __restrict__ hh,
                            const float* __restrict__ asrc,
                            const float* __restrict__ adst,
                            const float* __restrict__ bias,
                            __half* __restrict__ outh,
                            int nodeBase, int nodeEnd) {
    int node = nodeBase + ((blockIdx.x * blockDim.x + threadIdx.x) >> 5);
    int lane = threadIdx.x & 31;
    if (node >= nodeEnd) return;

    int beg = g_rowptr[node];
    int end = g_rowptr[node + 1];
    int hsel = lane >> 2;

    float adst_l = adst[node * HEADS + hsel];
    float tt = asrc[node * HEADS + hsel] + adst_l;
    float aself = (tt > 0.f) ? tt : NEG * tt;   // self-loop logit = stabilizer

    float denom = 0.f;
    float acc[8];
#pragma unroll
    for (int r = 0; r < 8; r++) acc[r] = 0.f;

    int j = beg;
    for (; j + 1 < end; j += 2) {
        int s0 = g_csrsrc[j];
        int s1v = g_csrsrc[j + 1];
        float a0 = asrc[s0 * HEADS + hsel] + adst_l;
        float a1 = asrc[s1v * HEADS + hsel] + adst_l;
        uint4 u0 = *((const uint4*)(hh + (size_t)s0 * HC1) + lane);
        uint4 u1 = *((const uint4*)(hh + (size_t)s1v * HC1) + lane);
        a0 = (a0 > 0.f) ? a0 : NEG * a0;
        a1 = (a1 > 0.f) ? a1 : NEG * a1;
        float ex0 = __expf(fminf(a0 - aself, 60.f));
        float ex1 = __expf(fminf(a1 - aself, 60.f));
        denom += ex0 + ex1;
        float2 f;
        f = __half22float2(*(__half2*)&u0.x); acc[0] = fmaf(f.x, ex0, acc[0]); acc[1] = fmaf(f.y, ex0, acc[1]);
        f = __half22float2(*(__half2*)&u0.y); acc[2] = fmaf(f.x, ex0, acc[2]); acc[3] = fmaf(f.y, ex0, acc[3]);
        f = __half22float2(*(__half2*)&u0.z); acc[4] = fmaf(f.x, ex0, acc[4]); acc[5] = fmaf(f.y, ex0, acc[5]);
        f = __half22float2(*(__half2*)&u0.w); acc[6] = fmaf(f.x, ex0, acc[6]); acc[7] = fmaf(f.y, ex0, acc[7]);
        f = __half22float2(*(__half2*)&u1.x); acc[0] = fmaf(f.x, ex1, acc[0]); acc[1] = fmaf(f.y, ex1, acc[1]);
        f = __half22float2(*(__half2*)&u1.y); acc[2] = fmaf(f.x, ex1, acc[2]); acc[3] = fmaf(f.y, ex1, acc[3]);
        f = __half22float2(*(__half2*)&u1.z); acc[4] = fmaf(f.x, ex1, acc[4]); acc[5] = fmaf(f.y, ex1, acc[5]);
        f = __half22float2(*(__half2*)&u1.w); acc[6] = fmaf(f.x, ex1, acc[6]); acc[7] = fmaf(f.y, ex1, acc[7]);
    }
    if (j < end) {
        int s = g_csrsrc[j];
        float a = asrc[s * HEADS + hsel] + adst_l;
        a = (a > 0.f) ? a : NEG * a;
        float ex = __expf(fminf(a - aself, 60.f));
        denom += ex;
        uint4 u = *((const uint4*)(hh + (size_t)s * HC1) + lane);
        float2 f;
        f = __half22float2(*(__half2*)&u.x); acc[0] = fmaf(f.x, ex, acc[0]); acc[1] = fmaf(f.y, ex, acc[1]);
        f = __half22float2(*(__half2*)&u.y); acc[2] = fmaf(f.x, ex, acc[2]); acc[3] = fmaf(f.y, ex, acc[3]);
        f = __half22float2(*(__half2*)&u.z); acc[4] = fmaf(f.x, ex, acc[4]); acc[5] = fmaf(f.y, ex, acc[5]);
        f = __half22float2(*(__half2*)&u.w); acc[6] = fmaf(f.x, ex, acc[6]); acc[7] = fmaf(f.y, ex, acc[7]);
    }

    float d = denom + 1e-16f;
    const float4* b4 = (const float4*)bias + lane * 2;
    float4 bb0 = b4[0], bb1 = b4[1];
    float o[8];
    o[0] = acc[0] / d + bb0.x; o[1] = acc[1] / d + bb0.y;
    o[2] = acc[2] / d + bb0.z; o[3] = acc[3] / d + bb0.w;
    o[4] = acc[4] / d + bb1.x; o[5] = acc[5] / d + bb1.y;
    o[6] = acc[6] / d + bb1.z; o[7] = acc[7] / d + bb1.w;
#pragma unroll
    for (int r = 0; r < 8; r++) o[r] = (o[r] > 0.f) ? o[r] : NEG * o[r];

    __half2 ho[4];
    ho[0] = __floats2half2_rn(o[0], o[1]);
    ho[1] = __floats2half2_rn(o[2], o[3]);
    ho[2] = __floats2half2_rn(o[4], o[5]);
    ho[3] = __floats2half2_rn(o[6], o[7]);
    *(uint4*)(outh + (size_t)node * HC1 + lane * 8) = *(uint4*)ho;
}

// ---------------- aggregation: layer 2 (C=4), fp16 gather, unroll 4 ---------
__global__ void agg2_kernel(const __half* __restrict__ hh,
                            const float* __restrict__ asrc,
                            const float* __restrict__ adst,
                            const float* __restrict__ bias,
                            float* __restrict__ out) {
    int warp = (blockIdx.x * blockDim.x + threadIdx.x) >> 5;
    int lane = threadIdx.x & 31;
    if (warp >= NN) return;

    int beg = g_rowptr[warp];
    int end = g_rowptr[warp + 1];
    int hd = lane >> 2;

    float adst_l = adst[warp * HEADS + hd];
    float tt = asrc[warp * HEADS + hd] + adst_l;
    float aself = (tt > 0.f) ? tt : NEG * tt;

    float denom = 0.f;
    float acc = 0.f;
    int j = beg;
    for (; j + 3 < end; j += 4) {
        int s0 = g_csrsrc[j], s1 = g_csrsrc[j + 1];
        int s2v = g_csrsrc[j + 2], s3 = g_csrsrc[j + 3];
        float a0 = asrc[s0 * HEADS + hd] + adst_l;
        float a1 = asrc[s1 * HEADS + hd] + adst_l;
        float a2 = asrc[s2v * HEADS + hd] + adst_l;
        float a3 = asrc[s3 * HEADS + hd] + adst_l;
        float v0 = __half2float(hh[(size_t)s0 * HC2 + lane]);
        float v1 = __half2float(hh[(size_t)s1 * HC2 + lane]);
        float v2 = __half2float(hh[(size_t)s2v * HC2 + lane]);
        float v3 = __half2float(hh[(size_t)s3 * HC2 + lane]);
        a0 = (a0 > 0.f) ? a0 : NEG * a0;
        a1 = (a1 > 0.f) ? a1 : NEG * a1;
        a2 = (a2 > 0.f) ? a2 : NEG * a2;
        a3 = (a3 > 0.f) ? a3 : NEG * a3;
        float ex0 = __expf(fminf(a0 - aself, 60.f));
        float ex1 = __expf(fminf(a1 - aself, 60.f));
        float ex2 = __expf(fminf(a2 - aself, 60.f));
        float ex3 = __expf(fminf(a3 - aself, 60.f));
        denom += (ex0 + ex1) + (ex2 + ex3);
        acc = fmaf(v0, ex0, acc);
        acc = fmaf(v1, ex1, acc);
        acc = fmaf(v2, ex2, acc);
        acc = fmaf(v3, ex3, acc);
    }
    for (; j < end; j++) {
        int s = g_csrsrc[j];
        float a = asrc[s * HEADS + hd] + adst_l;
        a = (a > 0.f) ? a : NEG * a;
        float ex = __expf(fminf(a - aself, 60.f));
        denom += ex;
        acc = fmaf(__half2float(hh[(size_t)s * HC2 + lane]), ex, acc);
    }

    out[(size_t)warp * HC2 + lane] = acc / (denom + 1e-16f) + bias[lane];
}

// ---------------- launch ------------------------------------------------------
extern "C" void kernel_launch(void* const* d_in, const int* in_sizes, int n_in,
                              void* d_out, int out_size) {
    const float* x      = (const float*)d_in[0];
    const int*   ei     = (const int*)d_in[1];
    const float* W1     = (const float*)d_in[2];
    const float* a_src1 = (const float*)d_in[3];
    const float* a_dst1 = (const float*)d_in[4];
    const float* b1     = (const float*)d_in[5];
    const float* W2     = (const float*)d_in[6];
    const float* a_src2 = (const float*)d_in[7];
    const float* a_dst2 = (const float*)d_in[8];
    const float* b2     = (const float*)d_in[9];
    float* out = (float*)d_out;

    const int* src = ei;
    const int* dst = ei + EE;

    float *as1, *ad1, *as2, *ad2;
    __half *h1h, *o1h, *h2h;
    cudaGetSymbolAddress((void**)&h1h, g_h1h);
    cudaGetSymbolAddress((void**)&o1h, g_o1h);
    cudaGetSymbolAddress((void**)&h2h, g_h2h);
    cudaGetSymbolAddress((void**)&as1, g_asrc1);
    cudaGetSymbolAddress((void**)&ad1, g_adst1);
    cudaGetSymbolAddress((void**)&as2, g_asrc2);
    cudaGetSymbolAddress((void**)&ad2, g_adst2);

    static cudaStream_t s2 = nullptr;
    static cudaEvent_t evFork = nullptr, evJoin = nullptr, evA = nullptr, evB = nullptr;
    if (s2 == nullptr) {
        cudaStreamCreateWithFlags(&s2, cudaStreamNonBlocking);
        cudaEventCreateWithFlags(&evFork, cudaEventDisableTiming);
        cudaEventCreateWithFlags(&evJoin, cudaEventDisableTiming);
        cudaEventCreateWithFlags(&evA, cudaEventDisableTiming);
        cudaEventCreateWithFlags(&evB, cudaEventDisableTiming);
    }

    // --- fork: CSR build on s2 (3 kernels), GEMM1 on main stream --------------
    cudaEventRecord(evFork, 0);
    cudaStreamWaitEvent(s2, evFork, 0);

    count_kernel<<<(EE + 255) / 256, 256, 0, s2>>>(dst);
    scan_fused_kernel<<<NBLK, SCAN_B, 0, s2>>>();
    scatter_kernel<<<(EE + 255) / 256, 256, 0, s2>>>(src, dst);
    cudaEventRecord(evJoin, s2);

    // main stream: GEMM1
    {
        dim3 grid(2, (NN + 127) / 128);
        gemm1_fused_kernel<<<grid, 256>>>(NN, x, W1, a_src1, a_dst1,
                                          h1h, as1, ad1);
    }

    // --- join, then half-split agg1 / gemm2 pipeline --------------------------
    cudaStreamWaitEvent(0, evJoin, 0);
    agg1_kernel<<<(NH0 * 32 + 255) / 256, 256>>>(h1h, as1, ad1, b1, o1h, 0, NH0);
    cudaEventRecord(evA, 0);
    agg1_kernel<<<((NN - NH0) * 32 + 255) / 256, 256>>>(h1h, as1, ad1, b1, o1h, NH0, NN);

    // side stream: gemm2 on first half (overlaps agg1 second half)
    cudaStreamWaitEvent(s2, evA, 0);
    {
        dim3 grid(1, NH0 / 128);
        gemm2_fp16_kernel<<<grid, 256, 0, s2>>>(0, NN, o1h, W2, a_src2, a_dst2,
                                                h2h, as2, ad2);
    }
    cudaEventRecord(evB, s2);

    // main stream: gemm2 on second half
    {
        dim3 grid(1, (NN - NH0 + 127) / 128);
        gemm2_fp16_kernel<<<grid, 256>>>(NH0, NN, o1h, W2, a_src2, a_dst2,
                                         h2h, as2, ad2);
    }

    // --- join both gemm2 halves, then agg2 -------------------------------------
    cudaStreamWaitEvent(0, evB, 0);
    agg2_kernel<<<(NN * 32 + 255) / 256, 256>>>(h2h, as2, ad2, b2, out);
}

// round 17
// speedup vs baseline: 1.0128x; 1.0002x over previous
#include <cuda_runtime.h>
#include <cuda_fp16.h>
#include <math.h>

// Problem constants (fixed shapes)
#define NN   50000
#define EE   800000
#define FIN  128
#define HEADS 8
#define HID  32
#define OUTC 4
#define HC1  (HEADS*HID)   // 256
#define HC2  (HEADS*OUTC)  // 32
#define NEG  0.2f

#define SCAN_B 1024
#define NBLK   ((NN + SCAN_B - 1) / SCAN_B)   // 49
#define NH0   25088                           // half-split boundary (196*128)

// ---------------- scratch (__device__ globals; no runtime allocation) -------
__device__ __half g_h1h[NN * HC1];      // fp16 h1
__device__ __half g_o1h[NN * HC1];      // fp16 o1 (agg1 output)
__device__ __half g_h2h[NN * HC2];      // fp16 h2
__device__ float  g_asrc1[NN * HEADS], g_adst1[NN * HEADS];
__device__ float  g_asrc2[NN * HEADS], g_adst2[NN * HEADS];
__device__ int    g_rowptr[NN + 1];
__device__ int    g_counts[NN];         // zero-init; re-zeroed by scan_fused
__device__ int    g_rank[EE];
__device__ int    g_csrsrc[EE + NN];
__device__ int    g_aggflag[2][NBLK];   // lookback flags (value+1), parity slots
__device__ int    g_runpar;             // toggled once per launch by count_kernel

// ---------------- mma helper -------------------------------------------------
__device__ __forceinline__ void mma16h(float* c, const unsigned* a, const unsigned* b) {
    asm volatile(
        "mma.sync.aligned.m16n8k16.row.col.f32.f16.f16.f32 "
        "{%0,%1,%2,%3}, {%4,%5,%6,%7}, {%8,%9}, {%0,%1,%2,%3};\n"
        : "+f"(c[0]), "+f"(c[1]), "+f"(c[2]), "+f"(c[3])
        : "r"(a[0]), "r"(a[1]), "r"(a[2]), "r"(a[3]), "r"(b[0]), "r"(b[1]));
}
__device__ __forceinline__ unsigned h2pack(float a, float b) {
    __half2 h = __floats2half2_rn(a, b);
    return *(unsigned*)&h;
}

// ===== GEMM1 (2-term fp16-split mma) fused with alphas1 + fp16 output =======
__global__ __launch_bounds__(256, 2)
void gemm1_fused_kernel(int M,
                        const float* __restrict__ A,
                        const float* __restrict__ B,
                        const float* __restrict__ a_src,
                        const float* __restrict__ a_dst,
                        __half* __restrict__ Ch,
                        float* __restrict__ asrc,
                        float* __restrict__ adst) {
    constexpr int BK = 32, K = FIN;
    constexpr int NT = 8;
    constexpr int AP = 18;
    constexpr int BP = 132;

    __shared__ unsigned Ah_s[128 * AP];
    __shared__ unsigned Bh_s[16 * BP], Bl_s[16 * BP];

    const int tid = threadIdx.x;
    const int wid = tid >> 5, lane = tid & 31;
    const int gq = lane >> 2, tig = lane & 3;
    const int warp_m = wid & 3, warp_n = wid >> 2;
    const int blockRow = blockIdx.y * 128;
    const int blockCol = blockIdx.x * 128;

    float acc[2][NT][4];
#pragma unroll
    for (int i = 0; i < 2; i++)
#pragma unroll
        for (int j = 0; j < NT; j++)
#pragma unroll
            for (int r = 0; r < 4; r++) acc[i][j][r] = 0.f;

    for (int k0 = 0; k0 < K; k0 += BK) {
        if (k0) __syncthreads();
#pragma unroll
        for (int l = 0; l < 4; l++) {
            int idx = tid + l * 256;
            int m = idx >> 3, kv = idx & 7;
            int gm = blockRow + m;
            float4 v = (gm < M) ? *(const float4*)&A[(size_t)gm * K + k0 + kv * 4]
                                : make_float4(0.f, 0.f, 0.f, 0.f);
            Ah_s[m * AP + kv * 2 + 0] = h2pack(v.x, v.y);
            Ah_s[m * AP + kv * 2 + 1] = h2pack(v.z, v.w);
        }
#pragma unroll
        for (int l = 0; l < 2; l++) {
            int idx = tid + l * 256;
            int k2 = idx >> 5, n4 = idx & 31;
            const float* r0 = &B[(size_t)(k0 + 2 * k2) * HC1 + blockCol + n4 * 4];
            const float* r1 = r0 + HC1;
            float4 v = *(const float4*)r0;
            float4 w = *(const float4*)r1;
            float va[4] = {v.x, v.y, v.z, v.w};
            float wa[4] = {w.x, w.y, w.z, w.w};
#pragma unroll
            for (int c = 0; c < 4; c++) {
                __half h0 = __float2half_rn(va[c]), h1 = __float2half_rn(wa[c]);
                __half2 hp = __halves2half2(h0, h1);
                Bh_s[k2 * BP + n4 * 4 + c] = *(unsigned*)&hp;
                Bl_s[k2 * BP + n4 * 4 + c] =
                    h2pack(va[c] - __half2float(h0), wa[c] - __half2float(h1));
            }
        }
        __syncthreads();

#pragma unroll
        for (int ks = 0; ks < 2; ks++) {
            const int kh2 = ks * 8;
            unsigned ah[2][4];
#pragma unroll
            for (int i = 0; i < 2; i++) {
                int m0 = warp_m * 32 + i * 16 + gq;
                ah[i][0] = Ah_s[(m0)     * AP + kh2 + tig];
                ah[i][1] = Ah_s[(m0 + 8) * AP + kh2 + tig];
                ah[i][2] = Ah_s[(m0)     * AP + kh2 + 4 + tig];
                ah[i][3] = Ah_s[(m0 + 8) * AP + kh2 + 4 + tig];
            }
#pragma unroll
            for (int j = 0; j < NT; j++) {
                int n = warp_n * 64 + j * 8 + gq;
                unsigned bh[2], bl[2];
                bh[0] = Bh_s[(kh2 + tig)     * BP + n];
                bh[1] = Bh_s[(kh2 + 4 + tig) * BP + n];
                bl[0] = Bl_s[(kh2 + tig)     * BP + n];
                bl[1] = Bl_s[(kh2 + 4 + tig) * BP + n];
#pragma unroll
                for (int i = 0; i < 2; i++) {
                    mma16h(acc[i][j], ah[i], bh);
                    mma16h(acc[i][j], ah[i], bl);
                }
            }
        }
    }

    // ---- fused epilogue ----------------------------------------------------
    float s1[2][2][2], s2[2][2][2];
#pragma unroll
    for (int i = 0; i < 2; i++)
#pragma unroll
        for (int rr = 0; rr < 2; rr++)
#pragma unroll
            for (int g = 0; g < 2; g++) { s1[i][rr][g] = 0.f; s2[i][rr][g] = 0.f; }

    const int headBase = (blockCol >> 5) + warp_n * 2;

#pragma unroll
    for (int j = 0; j < NT; j++) {
        int g = j >> 2;
        int head = headBase + g;
        int lc = (j & 3) * 8 + 2 * tig;
        float2 wsrc = *(const float2*)&a_src[head * HID + lc];
        float2 wdst = *(const float2*)&a_dst[head * HID + lc];
#pragma unroll
        for (int i = 0; i < 2; i++) {
            s1[i][0][g] += acc[i][j][0] * wsrc.x + acc[i][j][1] * wsrc.y;
            s1[i][1][g] += acc[i][j][2] * wsrc.x + acc[i][j][3] * wsrc.y;
            s2[i][0][g] += acc[i][j][0] * wdst.x + acc[i][j][1] * wdst.y;
            s2[i][1][g] += acc[i][j][2] * wdst.x + acc[i][j][3] * wdst.y;
        }
        int coloff = blockCol + warp_n * 64 + j * 8 + 2 * tig;
#pragma unroll
        for (int i = 0; i < 2; i++) {
            int row0 = blockRow + warp_m * 32 + i * 16 + gq;
            if (row0 < M)
                *(__half2*)&Ch[(size_t)row0 * HC1 + coloff] =
                    __floats2half2_rn(acc[i][j][0], acc[i][j][1]);
            if (row0 + 8 < M)
                *(__half2*)&Ch[(size_t)(row0 + 8) * HC1 + coloff] =
                    __floats2half2_rn(acc[i][j][2], acc[i][j][3]);
        }
    }

#pragma unroll
    for (int i = 0; i < 2; i++)
#pragma unroll
        for (int rr = 0; rr < 2; rr++)
#pragma unroll
            for (int g = 0; g < 2; g++) {
                float v1 = s1[i][rr][g], v2 = s2[i][rr][g];
                v1 += __shfl_xor_sync(0xffffffffu, v1, 1);
                v1 += __shfl_xor_sync(0xffffffffu, v1, 2);
                v2 += __shfl_xor_sync(0xffffffffu, v2, 1);
                v2 += __shfl_xor_sync(0xffffffffu, v2, 2);
                if (tig == 0) {
                    int row = blockRow + warp_m * 32 + i * 16 + gq + rr * 8;
                    if (row < M) {
                        asrc[row * HEADS + headBase + g] = v1;
                        adst[row * HEADS + headBase + g] = v2;
                    }
                }
            }
}

// ===== GEMM2 (fp16 mma) fused with alphas2 + fp16 output ====================
__global__ __launch_bounds__(256)
void gemm2_fp16_kernel(int rowBase, int M,
                       const __half* __restrict__ Ah,
                       const float* __restrict__ B,
                       const float* __restrict__ a_src,
                       const float* __restrict__ a_dst,
                       __half* __restrict__ Ch,
                       float* __restrict__ asrc,
                       float* __restrict__ adst) {
    constexpr int BK = 32, K = HC1, N = HC2;
    constexpr int NT = 2;
    constexpr int AP = 18;

    __shared__ unsigned As2[128 * AP];
    __shared__ __half  Bs[32][40];

    const int tid = threadIdx.x;
    const int wid = tid >> 5, lane = tid & 31;
    const int gq = lane >> 2, tig = lane & 3;
    const int warp_m = wid & 3, warp_n = wid >> 2;
    const int blockRow = rowBase + blockIdx.y * 128;

    float acc[2][NT][4];
#pragma unroll
    for (int i = 0; i < 2; i++)
#pragma unroll
        for (int j = 0; j < NT; j++)
#pragma unroll
            for (int r = 0; r < 4; r++) acc[i][j][r] = 0.f;

    for (int k0 = 0; k0 < K; k0 += BK) {
        if (k0) __syncthreads();
#pragma unroll
        for (int l = 0; l < 2; l++) {
            int idx = tid + l * 256;
            int m = idx >> 2, seg = idx & 3;
            int gm = blockRow + m;
            uint4 u = make_uint4(0u, 0u, 0u, 0u);
            if (gm < M) u = *(const uint4*)&Ah[(size_t)gm * K + k0 + seg * 8];
            As2[m * AP + seg * 4 + 0] = u.x;
            As2[m * AP + seg * 4 + 1] = u.y;
            As2[m * AP + seg * 4 + 2] = u.z;
            As2[m * AP + seg * 4 + 3] = u.w;
        }
        {
            int k = tid >> 3, n4 = tid & 7;
            float4 v = *(const float4*)&B[(size_t)(k0 + k) * N + n4 * 4];
            Bs[k][n4 * 4 + 0] = __float2half_rn(v.x);
            Bs[k][n4 * 4 + 1] = __float2half_rn(v.y);
            Bs[k][n4 * 4 + 2] = __float2half_rn(v.z);
            Bs[k][n4 * 4 + 3] = __float2half_rn(v.w);
        }
        __syncthreads();

#pragma unroll
        for (int ks = 0; ks < 2; ks++) {
            const int kh2 = ks * 8;
            const int kk = ks * 16;
            unsigned a[2][4];
#pragma unroll
            for (int i = 0; i < 2; i++) {
                int m0 = warp_m * 32 + i * 16 + gq;
                a[i][0] = As2[(m0)     * AP + kh2 + tig];
                a[i][1] = As2[(m0 + 8) * AP + kh2 + tig];
                a[i][2] = As2[(m0)     * AP + kh2 + 4 + tig];
                a[i][3] = As2[(m0 + 8) * AP + kh2 + 4 + tig];
            }
#pragma unroll
            for (int j = 0; j < NT; j++) {
                int n = warp_n * 16 + j * 8 + gq;
                __half2 hb0 = __halves2half2(Bs[kk + 2 * tig][n], Bs[kk + 2 * tig + 1][n]);
                __half2 hb1 = __halves2half2(Bs[kk + 2 * tig + 8][n], Bs[kk + 2 * tig + 9][n]);
                unsigned b[2] = {*(unsigned*)&hb0, *(unsigned*)&hb1};
#pragma unroll
                for (int i = 0; i < 2; i++)
                    mma16h(acc[i][j], a[i], b);
            }
        }
    }

#pragma unroll
    for (int j = 0; j < NT; j++) {
        int head = warp_n * 4 + 2 * j + (tig >> 1);
        float2 wsrc = *(const float2*)&a_src[head * OUTC + 2 * (tig & 1)];
        float2 wdst = *(const float2*)&a_dst[head * OUTC + 2 * (tig & 1)];
        int coloff = warp_n * 16 + j * 8 + 2 * tig;
#pragma unroll
        for (int i = 0; i < 2; i++) {
#pragma unroll
            for (int rr = 0; rr < 2; rr++) {
                float p1 = acc[i][j][2 * rr] * wsrc.x + acc[i][j][2 * rr + 1] * wsrc.y;
                float p2 = acc[i][j][2 * rr] * wdst.x + acc[i][j][2 * rr + 1] * wdst.y;
                p1 += __shfl_xor_sync(0xffffffffu, p1, 1);
                p2 += __shfl_xor_sync(0xffffffffu, p2, 1);
                int row = blockRow + warp_m * 32 + i * 16 + gq + rr * 8;
                if ((tig & 1) == 0 && row < M) {
                    asrc[row * HEADS + head] = p1;
                    adst[row * HEADS + head] = p2;
                }
            }
            int row0 = blockRow + warp_m * 32 + i * 16 + gq;
            if (row0 < M)
                *(__half2*)&Ch[(size_t)row0 * N + coloff] =
                    __floats2half2_rn(acc[i][j][0], acc[i][j][1]);
            if (row0 + 8 < M)
                *(__half2*)&Ch[(size_t)(row0 + 8) * N + coloff] =
                    __floats2half2_rn(acc[i][j][2], acc[i][j][3]);
        }
    }
}

// ---------------- CSR construction ------------------------------------------
// count: 1 edge/thread (round-14 proven) + per-launch parity toggle.
__global__ void count_kernel(const int* __restrict__ dst) {
    int e = blockIdx.x * blockDim.x + threadIdx.x;
    if (e == 0) g_runpar ^= 1;   // once per launch; consumed by scan_fused later
    if (e < EE) g_rank[e] = atomicAdd(&g_counts[dst[e]], 1);
}

// Fused block-scan + aggregate-lookback + finalize. grid = NBLK, block = 1024.
// Each block publishes its local sum to g_aggflag[par][b] (value+1), then
// warp-sums all lower blocks' aggregates (spin until published). Blocks only
// wait on lower bids (launched first) -> no circular wait. Parity slots make
// this graph-replay safe; each run clears the other slot for the next run.
__global__ void scan_fused_kernel() {
    __shared__ int sh[SCAN_B];
    __shared__ int s_off;
    const int t = threadIdx.x;
    const int b = blockIdx.x;
    const int par = g_runpar & 1;
    int i = b * SCAN_B + t;
    int v = (i < NN) ? (g_counts[i] + 1) : 0;   // +1 self loop
    sh[t] = v;
    __syncthreads();
    for (int off = 1; off < SCAN_B; off <<= 1) {
        int x = (t >= off) ? sh[t - off] : 0;
        __syncthreads();
        sh[t] += x;
        __syncthreads();
    }
    // publish this block's aggregate (inclusive total), as value+1
    if (t == 0) {
        int total = sh[SCAN_B - 1];
        __threadfence();
        atomicExch(&g_aggflag[par][b], total + 1);
    }
    // lookback: sum aggregates of blocks [0, b)
    if (t < 32) {
        int sum = 0;
        for (int q = t; q < b; q += 32) {
            int f;
            do { f = atomicAdd(&g_aggflag[par][q], 0); } while (f == 0);
            sum += f - 1;
        }
#pragma unroll
        for (int o = 16; o > 0; o >>= 1)
            sum += __shfl_down_sync(0xffffffffu, sum, o);
        if (t == 0) s_off = sum;
    }
    __syncthreads();
    int off = s_off;
    if (i == 0) g_rowptr[0] = 0;
    if (i < NN) {
        int e = sh[t] + off;
        g_rowptr[i + 1] = e;
        int begin = e - v;
        g_csrsrc[begin] = i;        // self loop first
        g_counts[i] = 0;            // re-zero histogram for the next replay
    }
    if (t == 0) g_aggflag[par ^ 1][b] = 0;   // clear other slot for next run
}

// scatter: 1 edge/thread (round-14 proven).
__global__ void scatter_kernel(const int* __restrict__ src,
                               const int* __restrict__ dst) {
    int e = blockIdx.x * blockDim.x + threadIdx.x;
    if (e < EE) {
        int d = dst[e];
        g_csrsrc[g_rowptr[d] + 1 + g_rank[e]] = src[e];
    }
}

// ---------------- aggregation: layer 1, warp per node, unroll 2 -------------
__global__ void agg1_kernel(const __half* __restrict__ hh,
                            const float* __restrict__ asrc,
                            const float* __restrict__ adst,
                            const float* __restrict__ bias,
                            __half* __restrict__ outh,
                            int nodeBase, int nodeEnd) {
    int node = nodeBase + ((blockIdx.x * blockDim.x + threadIdx.x) >> 5);
    int lane = threadIdx.x & 31;
    if (node >= nodeEnd) return;

    int beg = g_rowptr[node];
    int end = g_rowptr[node + 1];
    int hsel = lane >> 2;

    float adst_l = adst[node * HEADS + hsel];
    float tt = asrc[node * HEADS + hsel] + adst_l;
    float aself = (tt > 0.f) ? tt : NEG * tt;   // self-loop logit = stabilizer

    float denom = 0.f;
    float acc[8];
#pragma unroll
    for (int r = 0; r < 8; r++) acc[r] = 0.f;

    int j = beg;
    for (; j + 1 < end; j += 2) {
        int s0 = g_csrsrc[j];
        int s1v = g_csrsrc[j + 1];
        float a0 = asrc[s0 * HEADS + hsel] + adst_l;
        float a1 = asrc[s1v * HEADS + hsel] + adst_l;
        uint4 u0 = *((const uint4*)(hh + (size_t)s0 * HC1) + lane);
        uint4 u1 = *((const uint4*)(hh + (size_t)s1v * HC1) + lane);
        a0 = (a0 > 0.f) ? a0 : NEG * a0;
        a1 = (a1 > 0.f) ? a1 : NEG * a1;
        float ex0 = __expf(fminf(a0 - aself, 60.f));
        float ex1 = __expf(fminf(a1 - aself, 60.f));
        denom += ex0 + ex1;
        float2 f;
        f = __half22float2(*(__half2*)&u0.x); acc[0] = fmaf(f.x, ex0, acc[0]); acc[1] = fmaf(f.y, ex0, acc[1]);
        f = __half22float2(*(__half2*)&u0.y); acc[2] = fmaf(f.x, ex0, acc[2]); acc[3] = fmaf(f.y, ex0, acc[3]);
        f = __half22float2(*(__half2*)&u0.z); acc[4] = fmaf(f.x, ex0, acc[4]); acc[5] = fmaf(f.y, ex0, acc[5]);
        f = __half22float2(*(__half2*)&u0.w); acc[6] = fmaf(f.x, ex0, acc[6]); acc[7] = fmaf(f.y, ex0, acc[7]);
        f = __half22float2(*(__half2*)&u1.x); acc[0] = fmaf(f.x, ex1, acc[0]); acc[1] = fmaf(f.y, ex1, acc[1]);
        f = __half22float2(*(__half2*)&u1.y); acc[2] = fmaf(f.x, ex1, acc[2]); acc[3] = fmaf(f.y, ex1, acc[3]);
        f = __half22float2(*(__half2*)&u1.z); acc[4] = fmaf(f.x, ex1, acc[4]); acc[5] = fmaf(f.y, ex1, acc[5]);
        f = __half22float2(*(__half2*)&u1.w); acc[6] = fmaf(f.x, ex1, acc[6]); acc[7] = fmaf(f.y, ex1, acc[7]);
    }
    if (j < end) {
        int s = g_csrsrc[j];
        float a = asrc[s * HEADS + hsel] + adst_l;
        a = (a > 0.f) ? a : NEG * a;
        float ex = __expf(fminf(a - aself, 60.f));
        denom += ex;
        uint4 u = *((const uint4*)(hh + (size_t)s * HC1) + lane);
        float2 f;
        f = __half22float2(*(__half2*)&u.x); acc[0] = fmaf(f.x, ex, acc[0]); acc[1] = fmaf(f.y, ex, acc[1]);
        f = __half22float2(*(__half2*)&u.y); acc[2] = fmaf(f.x, ex, acc[2]); acc[3] = fmaf(f.y, ex, acc[3]);
        f = __half22float2(*(__half2*)&u.z); acc[4] = fmaf(f.x, ex, acc[4]); acc[5] = fmaf(f.y, ex, acc[5]);
        f = __half22float2(*(__half2*)&u.w); acc[6] = fmaf(f.x, ex, acc[6]); acc[7] = fmaf(f.y, ex, acc[7]);
    }

    float d = denom + 1e-16f;
    const float4* b4 = (const float4*)bias + lane * 2;
    float4 bb0 = b4[0], bb1 = b4[1];
    float o[8];
    o[0] = acc[0] / d + bb0.x; o[1] = acc[1] / d + bb0.y;
    o[2] = acc[2] / d + bb0.z; o[3] = acc[3] / d + bb0.w;
    o[4] = acc[4] / d + bb1.x; o[5] = acc[5] / d + bb1.y;
    o[6] = acc[6] / d + bb1.z; o[7] = acc[7] / d + bb1.w;
#pragma unroll
    for (int r = 0; r < 8; r++) o[r] = (o[r] > 0.f) ? o[r] : NEG * o[r];

    __half2 ho[4];
    ho[0] = __floats2half2_rn(o[0], o[1]);
    ho[1] = __floats2half2_rn(o[2], o[3]);
    ho[2] = __floats2half2_rn(o[4], o[5]);
    ho[3] = __floats2half2_rn(o[6], o[7]);
    *(uint4*)(outh + (size_t)node * HC1 + lane * 8) = *(uint4*)ho;
}

// ---------------- aggregation: layer 2 (C=4), fp16 gather, unroll 4 ---------
__global__ void agg2_kernel(const __half* __restrict__ hh,
                            const float* __restrict__ asrc,
                            const float* __restrict__ adst,
                            const float* __restrict__ bias,
                            float* __restrict__ out) {
    int warp = (blockIdx.x * blockDim.x + threadIdx.x) >> 5;
    int lane = threadIdx.x & 31;
    if (warp >= NN) return;

    int beg = g_rowptr[warp];
    int end = g_rowptr[warp + 1];
    int hd = lane >> 2;

    float adst_l = adst[warp * HEADS + hd];
    float tt = asrc[warp * HEADS + hd] + adst_l;
    float aself = (tt > 0.f) ? tt : NEG * tt;

    float denom = 0.f;
    float acc = 0.f;
    int j = beg;
    for (; j + 3 < end; j += 4) {
        int s0 = g_csrsrc[j], s1 = g_csrsrc[j + 1];
        int s2v = g_csrsrc[j + 2], s3 = g_csrsrc[j + 3];
        float a0 = asrc[s0 * HEADS + hd] + adst_l;
        float a1 = asrc[s1 * HEADS + hd] + adst_l;
        float a2 = asrc[s2v * HEADS + hd] + adst_l;
        float a3 = asrc[s3 * HEADS + hd] + adst_l;
        float v0 = __half2float(hh[(size_t)s0 * HC2 + lane]);
        float v1 = __half2float(hh[(size_t)s1 * HC2 + lane]);
        float v2 = __half2float(hh[(size_t)s2v * HC2 + lane]);
        float v3 = __half2float(hh[(size_t)s3 * HC2 + lane]);
        a0 = (a0 > 0.f) ? a0 : NEG * a0;
        a1 = (a1 > 0.f) ? a1 : NEG * a1;
        a2 = (a2 > 0.f) ? a2 : NEG * a2;
        a3 = (a3 > 0.f) ? a3 : NEG * a3;
        float ex0 = __expf(fminf(a0 - aself, 60.f));
        float ex1 = __expf(fminf(a1 - aself, 60.f));
        float ex2 = __expf(fminf(a2 - aself, 60.f));
        float ex3 = __expf(fminf(a3 - aself, 60.f));
        denom += (ex0 + ex1) + (ex2 + ex3);
        acc = fmaf(v0, ex0, acc);
        acc = fmaf(v1, ex1, acc);
        acc = fmaf(v2, ex2, acc);
        acc = fmaf(v3, ex3, acc);
    }
    for (; j < end; j++) {
        int s = g_csrsrc[j];
        float a = asrc[s * HEADS + hd] + adst_l;
        a = (a > 0.f) ? a : NEG * a;
        float ex = __expf(fminf(a - aself, 60.f));
        denom += ex;
        acc = fmaf(__half2float(hh[(size_t)s * HC2 + lane]), ex, acc);
    }

    out[(size_t)warp * HC2 + lane] = acc / (denom + 1e-16f) + bias[lane];
}

// ---------------- launch ------------------------------------------------------
extern "C" void kernel_launch(void* const* d_in, const int* in_sizes, int n_in,
                              void* d_out, int out_size) {
    const float* x      = (const float*)d_in[0];
    const int*   ei     = (const int*)d_in[1];
    const float* W1     = (const float*)d_in[2];
    const float* a_src1 = (const float*)d_in[3];
    const float* a_dst1 = (const float*)d_in[4];
    const float* b1     = (const float*)d_in[5];
    const float* W2     = (const float*)d_in[6];
    const float* a_src2 = (const float*)d_in[7];
    const float* a_dst2 = (const float*)d_in[8];
    const float* b2     = (const float*)d_in[9];
    float* out = (float*)d_out;

    const int* src = ei;
    const int* dst = ei + EE;

    float *as1, *ad1, *as2, *ad2;
    __half *h1h, *o1h, *h2h;
    cudaGetSymbolAddress((void**)&h1h, g_h1h);
    cudaGetSymbolAddress((void**)&o1h, g_o1h);
    cudaGetSymbolAddress((void**)&h2h, g_h2h);
    cudaGetSymbolAddress((void**)&as1, g_asrc1);
    cudaGetSymbolAddress((void**)&ad1, g_adst1);
    cudaGetSymbolAddress((void**)&as2, g_asrc2);
    cudaGetSymbolAddress((void**)&ad2, g_adst2);

    static cudaStream_t s2 = nullptr;
    static cudaEvent_t evFork = nullptr, evJoin = nullptr, evA = nullptr, evB = nullptr;
    if (s2 == nullptr) {
        cudaStreamCreateWithFlags(&s2, cudaStreamNonBlocking);
        cudaEventCreateWithFlags(&evFork, cudaEventDisableTiming);
        cudaEventCreateWithFlags(&evJoin, cudaEventDisableTiming);
        cudaEventCreateWithFlags(&evA, cudaEventDisableTiming);
        cudaEventCreateWithFlags(&evB, cudaEventDisableTiming);
    }

    // --- fork: CSR build on s2 (3 kernels), GEMM1 on main stream --------------
    cudaEventRecord(evFork, 0);
    cudaStreamWaitEvent(s2, evFork, 0);

    count_kernel<<<(EE + 255) / 256, 256, 0, s2>>>(dst);
    scan_fused_kernel<<<NBLK, SCAN_B, 0, s2>>>();
    scatter_kernel<<<(EE + 255) / 256, 256, 0, s2>>>(src, dst);
    cudaEventRecord(evJoin, s2);

    // main stream: GEMM1
    {
        dim3 grid(2, (NN + 127) / 128);
        gemm1_fused_kernel<<<grid, 256>>>(NN, x, W1, a_src1, a_dst1,
                                          h1h, as1, ad1);
    }

    // --- join, then half-split agg1 / gemm2 pipeline --------------------------
    cudaStreamWaitEvent(0, evJoin, 0);
    agg1_kernel<<<(NH0 * 32 + 255) / 256, 256>>>(h1h, as1, ad1, b1, o1h, 0, NH0);
    cudaEventRecord(evA, 0);
    agg1_kernel<<<((NN - NH0) * 32 + 255) / 256, 256>>>(h1h, as1, ad1, b1, o1h, NH0, NN);

    // side stream: gemm2 on first half (overlaps agg1 second half)
    cudaStreamWaitEvent(s2, evA, 0);
    {
        dim3 grid(1, NH0 / 128);
        gemm2_fp16_kernel<<<grid, 256, 0, s2>>>(0, NN, o1h, W2, a_src2, a_dst2,
                                                h2h, as2, ad2);
    }
    cudaEventRecord(evB, s2);

    // main stream: gemm2 on second half
    {
        dim3 grid(1, (NN - NH0 + 127) / 128);
        gemm2_fp16_kernel<<<grid, 256>>>(NH0, NN, o1h, W2, a_src2, a_dst2,
                                         h2h, as2, ad2);
    }

    // --- join both gemm2 halves, then agg2 -------------------------------------
    cudaStreamWaitEvent(0, evB, 0);
    agg2_kernel<<<(NN * 32 + 255) / 256, 256>>>(h2h, as2, ad2, b2, out);
}